// round 3
// baseline (speedup 1.0000x reference)
#include <cuda_runtime.h>
#include <cstdint>

#define LATENT   128
#define HIDDEN   256
#define NTYPES   32
#define ETYPES   8
#define TILE_E   64
#define KC       16
#define NCHUNK   (2 * LATENT / KC)   // 16
#define THREADS  256
#define HSTRIDE  264   // padded row stride for feat/h buffer (16B-aligned rows)
#define W2STRIDE 260   // padded row stride for transposed W2

// ---------------- packed f32x2 helpers (Blackwell FFMA2) ----------------
__device__ __forceinline__ unsigned long long fma2(unsigned long long a,
                                                   unsigned long long b,
                                                   unsigned long long c) {
    unsigned long long d;
    asm("fma.rn.f32x2 %0, %1, %2, %3;" : "=l"(d) : "l"(a), "l"(b), "l"(c));
    return d;
}
__device__ __forceinline__ unsigned long long pack2(float lo, float hi) {
    unsigned long long d;
    asm("mov.b64 %0, {%1, %2};" : "=l"(d) : "f"(lo), "f"(hi));
    return d;
}
__device__ __forceinline__ float2 unpack2(unsigned long long v) {
    float2 r;
    asm("mov.b64 {%0, %1}, %2;" : "=f"(r.x), "=f"(r.y) : "l"(v));
    return r;
}

// ---------------- node logits: z @ W_node + b_node ----------------
__global__ void node_kernel(const float* __restrict__ z,
                            const float* __restrict__ Wn,
                            const float* __restrict__ bn,
                            float* __restrict__ out,
                            int n_nodes) {
    __shared__ float ws[LATENT * NTYPES];
    __shared__ float zs[32 * 132];
    __shared__ float bs[NTYPES];

    int tid = threadIdx.x;
    for (int idx = tid; idx < LATENT * NTYPES / 4; idx += THREADS)
        ((float4*)ws)[idx] = ((const float4*)Wn)[idx];
    if (tid < NTYPES) bs[tid] = bn[tid];

    long long nBase = (long long)blockIdx.x * 32;
    for (int idx = tid; idx < 32 * LATENT / 4; idx += THREADS) {
        int n = idx / (LATENT / 4), kk = idx % (LATENT / 4);
        long long gn = nBase + n;
        float4 v = make_float4(0.f, 0.f, 0.f, 0.f);
        if (gn < n_nodes) v = *(const float4*)(z + gn * LATENT + kk * 4);
        *(float4*)(zs + n * 132 + kk * 4) = v;
    }
    __syncthreads();

    int n  = tid >> 3;
    int tg = tid & 7;
    float a0 = bs[tg * 4 + 0], a1 = bs[tg * 4 + 1];
    float a2 = bs[tg * 4 + 2], a3 = bs[tg * 4 + 3];
    const float* zr = zs + n * 132;
#pragma unroll 8
    for (int k = 0; k < LATENT; k++) {
        float zv = zr[k];
        float4 w = *(const float4*)(ws + k * NTYPES + tg * 4);
        a0 = fmaf(zv, w.x, a0);
        a1 = fmaf(zv, w.y, a1);
        a2 = fmaf(zv, w.z, a2);
        a3 = fmaf(zv, w.w, a3);
    }
    long long gn = nBase + n;
    if (gn < n_nodes) {
        float4 o4 = make_float4(a0, a1, a2, a3);
        *(float4*)(out + gn * NTYPES + tg * 4) = o4;
    }
}

// ---------------- edge MLP ----------------
// 256 threads, TILE_E=64 edges. Thread (eg=tid/32, jg=tid%32): 8 edges x 8 cols.
// Double-buffered W1 staging (KC=16), float4 feat reads, 4-kc register-hoisted W1.
__global__ void __launch_bounds__(THREADS, 2)
edge_kernel(const float* __restrict__ z,
            const int* __restrict__ ei,
            const float* __restrict__ W1,
            const float* __restrict__ b1,
            const float* __restrict__ W2,
            const float* __restrict__ b2,
            float* __restrict__ out,
            int n_edges, int n_nodes) {
    extern __shared__ float smem[];
    float* feat = smem;                          // TILE_E * HSTRIDE (reused for h)
    float* w1s  = feat + TILE_E * HSTRIDE;       // 2 * KC * HIDDEN (double buffer)
    float* ws2t = w1s + 2 * KC * HIDDEN;         // ETYPES * W2STRIDE

    int tid  = threadIdx.x;
    int lane = tid & 31;
    int warp = tid >> 5;
    long long eBase = (long long)blockIdx.x * TILE_E;

    // stage W2 transposed
    for (int idx = tid; idx < HIDDEN * ETYPES; idx += THREADS) {
        int k = idx / ETYPES, o = idx % ETYPES;
        ws2t[o * W2STRIDE + k] = W2[idx];
    }

    // gather edge features
#pragma unroll
    for (int i = 0; i < 8; i++) {
        long long e = eBase + warp * 8 + i;
        if (e >= n_edges) e = n_edges - 1;
        int r = ei[e];
        int c = ei[(long long)n_edges + e];
        r = min(max(r, 0), n_nodes - 1);
        c = min(max(c, 0), n_nodes - 1);
        float4 vr = *(const float4*)(z + (long long)r * LATENT + lane * 4);
        float4 vc = *(const float4*)(z + (long long)c * LATENT + lane * 4);
        float* fe = feat + (warp * 8 + i) * HSTRIDE;
        *(float4*)(fe + lane * 4)          = vr;
        *(float4*)(fe + LATENT + lane * 4) = vc;
    }

    int jg = tid & 31;
    int eg = tid >> 5;

    // accumulators init with bias
    unsigned long long acc[8][4];
    {
        float4 bA = *(const float4*)(b1 + jg * 8);
        float4 bB = *(const float4*)(b1 + jg * 8 + 4);
        unsigned long long i0 = pack2(bA.x, bA.y);
        unsigned long long i1 = pack2(bA.z, bA.w);
        unsigned long long i2 = pack2(bB.x, bB.y);
        unsigned long long i3 = pack2(bB.z, bB.w);
#pragma unroll
        for (int i = 0; i < 8; i++) {
            acc[i][0] = i0; acc[i][1] = i1; acc[i][2] = i2; acc[i][3] = i3;
        }
    }

    // prologue: stage chunk 0 into buffer 0
    {
        const float4* src = (const float4*)W1;
        float4* dst = (float4*)w1s;
#pragma unroll
        for (int u = 0; u < KC * HIDDEN / 4 / THREADS; u++)
            dst[tid + u * THREADS] = src[tid + u * THREADS];
    }
    __syncthreads();

    const float* feb = feat + eg * 8 * HSTRIDE;

    for (int c = 0; c < NCHUNK; c++) {
        // prefetch next chunk into registers (overlaps with compute)
        float4 pre[KC * HIDDEN / 4 / THREADS];
        if (c + 1 < NCHUNK) {
            const float4* src = (const float4*)(W1 + (c + 1) * KC * HIDDEN);
#pragma unroll
            for (int u = 0; u < KC * HIDDEN / 4 / THREADS; u++)
                pre[u] = src[tid + u * THREADS];
        }

        const float* w1cur = w1s + (c & 1) * KC * HIDDEN;
        int kk = c * KC;

#pragma unroll
        for (int kq = 0; kq < KC; kq += 4) {
            // hoist 4 kc of W1 (this thread's 8 cols) into registers
            ulonglong2 wv[4][2];
#pragma unroll
            for (int t = 0; t < 4; t++) {
                const float* wrow = w1cur + (kq + t) * HIDDEN + jg * 8;
                wv[t][0] = *(const ulonglong2*)wrow;
                wv[t][1] = *(const ulonglong2*)(wrow + 4);
            }
#pragma unroll
            for (int i = 0; i < 8; i++) {
                float4 f = *(const float4*)(feb + i * HSTRIDE + kk + kq);
                unsigned long long f0 = pack2(f.x, f.x);
                unsigned long long f1 = pack2(f.y, f.y);
                unsigned long long f2 = pack2(f.z, f.z);
                unsigned long long f3 = pack2(f.w, f.w);
                acc[i][0] = fma2(f0, wv[0][0].x, acc[i][0]);
                acc[i][1] = fma2(f0, wv[0][0].y, acc[i][1]);
                acc[i][2] = fma2(f0, wv[0][1].x, acc[i][2]);
                acc[i][3] = fma2(f0, wv[0][1].y, acc[i][3]);
                acc[i][0] = fma2(f1, wv[1][0].x, acc[i][0]);
                acc[i][1] = fma2(f1, wv[1][0].y, acc[i][1]);
                acc[i][2] = fma2(f1, wv[1][1].x, acc[i][2]);
                acc[i][3] = fma2(f1, wv[1][1].y, acc[i][3]);
                acc[i][0] = fma2(f2, wv[2][0].x, acc[i][0]);
                acc[i][1] = fma2(f2, wv[2][0].y, acc[i][1]);
                acc[i][2] = fma2(f2, wv[2][1].x, acc[i][2]);
                acc[i][3] = fma2(f2, wv[2][1].y, acc[i][3]);
                acc[i][0] = fma2(f3, wv[3][0].x, acc[i][0]);
                acc[i][1] = fma2(f3, wv[3][0].y, acc[i][1]);
                acc[i][2] = fma2(f3, wv[3][1].x, acc[i][2]);
                acc[i][3] = fma2(f3, wv[3][1].y, acc[i][3]);
            }
        }

        // write prefetched chunk into the other buffer
        if (c + 1 < NCHUNK) {
            float4* dst = (float4*)(w1s + ((c + 1) & 1) * KC * HIDDEN);
#pragma unroll
            for (int u = 0; u < KC * HIDDEN / 4 / THREADS; u++)
                dst[tid + u * THREADS] = pre[u];
        }
        __syncthreads();
    }

    // ReLU + store h into feat buffer (reuse)
#pragma unroll
    for (int i = 0; i < 8; i++) {
        float* hrow = feat + (eg * 8 + i) * HSTRIDE + jg * 8;
#pragma unroll
        for (int c = 0; c < 4; c++) {
            float2 v = unpack2(acc[i][c]);
            hrow[c * 2 + 0] = fmaxf(v.x, 0.f);
            hrow[c * 2 + 1] = fmaxf(v.y, 0.f);
        }
    }
    __syncthreads();

    // GEMM2: h[64 x 256] @ W2[256 x 8] + b2
    int e0 = tid >> 3, o = tid & 7;
    float bo = b2[o];
#pragma unroll
    for (int pass = 0; pass < 2; pass++) {
        int e = e0 + pass * 32;
        const float* hr = feat + e * HSTRIDE;
        const float* wr = ws2t + o * W2STRIDE;
        float a = bo;
#pragma unroll 8
        for (int k = 0; k < HIDDEN; k += 4) {
            float4 hv = *(const float4*)(hr + k);
            float4 wv = *(const float4*)(wr + k);
            a = fmaf(hv.x, wv.x, a);
            a = fmaf(hv.y, wv.y, a);
            a = fmaf(hv.z, wv.z, a);
            a = fmaf(hv.w, wv.w, a);
        }
        long long ge = eBase + e;
        if (ge < n_edges) out[ge * ETYPES + o] = a;
    }
}

// ---------------- launch ----------------
extern "C" void kernel_launch(void* const* d_in, const int* in_sizes, int n_in,
                              void* d_out, int out_size) {
    const float* z  = (const float*)d_in[0];
    const int*   ei = (const int*)d_in[1];
    const float* Wn = (const float*)d_in[2];
    const float* bn = (const float*)d_in[3];
    const float* W1 = (const float*)d_in[4];
    const float* b1 = (const float*)d_in[5];
    const float* W2 = (const float*)d_in[6];
    const float* b2 = (const float*)d_in[7];

    int n_nodes = in_sizes[0] / LATENT;
    int n_edges = in_sizes[1] / 2;
    float* out = (float*)d_out;

    node_kernel<<<(n_nodes + 31) / 32, THREADS>>>(z, Wn, bn, out, n_nodes);

    size_t smem_bytes = (size_t)(TILE_E * HSTRIDE + 2 * KC * HIDDEN + ETYPES * W2STRIDE) * sizeof(float);
    cudaFuncSetAttribute(edge_kernel, cudaFuncAttributeMaxDynamicSharedMemorySize, (int)smem_bytes);
    edge_kernel<<<(n_edges + TILE_E - 1) / TILE_E, THREADS, smem_bytes>>>(
        z, ei, W1, b1, W2, b2, out + (size_t)n_nodes * NTYPES, n_edges, n_nodes);
}

// round 6
// speedup vs baseline: 1.8736x; 1.8736x over previous
#include <cuda_runtime.h>
#include <cuda_bf16.h>
#include <cstdint>

#define LATENT   128
#define HIDDEN   256
#define NTYPES   32
#define ETYPES   8
#define E_TILE   64
#define THREADS  256
#define ASTRIDE  264          // bf16 elems per A row (pad: conflict-free ldmatrix)
#define HSTRIDE  264          // f32 elems per h row
#define W2STRIDE 260
#define KSTEPS   16           // K=256 in 16 k16-steps
#define CHUNK_S  4            // k16-steps per B chunk
#define NCHK     4

// dynamic smem layout (bytes):
//  A_hi: 64*264*2 = 33792   @0
//  A_lo: 33792              @33792
//  Bbuf0: 65536 (hi 32768 | lo 32768)  @67584
//  Bbuf1: 65536                        @133120
//  h overlay (f32 64x264) @67584 after final barrier
#define SM_ALO   33792
#define SM_B0    67584
#define SM_BBYTES 65536
#define DSMEM_BYTES (67584 + 2 * 65536)

// fragment-ready packed W1 (hi/lo), u32 words:
// word idx = (((s*32 + T)*32 + lane)*2 + q), s=k16 step, T=n8 tile, q=b0/b1
__device__ unsigned int g_Bh[32768];
__device__ unsigned int g_Bl[32768];

__device__ __forceinline__ unsigned int smem_u32(const void* p) {
    unsigned int a;
    asm("{ .reg .u64 t; cvta.to.shared.u64 t, %1; cvt.u32.u64 %0, t; }" : "=r"(a) : "l"(p));
    return a;
}
__device__ __forceinline__ unsigned int pack_bf16x2(float lo_elem, float hi_elem) {
    // low half = first element
    __nv_bfloat16 b0 = __float2bfloat16(lo_elem);
    __nv_bfloat16 b1 = __float2bfloat16(hi_elem);
    unsigned short u0 = *reinterpret_cast<unsigned short*>(&b0);
    unsigned short u1 = *reinterpret_cast<unsigned short*>(&b1);
    return (unsigned int)u0 | ((unsigned int)u1 << 16);
}
__device__ __forceinline__ float bf16hi_f(float v) {
    __nv_bfloat16 b = __float2bfloat16(v);
    return __bfloat162float(b);
}
__device__ __forceinline__ void mma_bf16(float* c, const unsigned int* a,
                                         unsigned int b0, unsigned int b1) {
    asm volatile(
        "mma.sync.aligned.m16n8k16.row.col.f32.bf16.bf16.f32 "
        "{%0,%1,%2,%3}, {%4,%5,%6,%7}, {%8,%9}, {%0,%1,%2,%3};"
        : "+f"(c[0]), "+f"(c[1]), "+f"(c[2]), "+f"(c[3])
        : "r"(a[0]), "r"(a[1]), "r"(a[2]), "r"(a[3]), "r"(b0), "r"(b1));
}
__device__ __forceinline__ void ldmatrix4(unsigned int* r, unsigned int addr) {
    asm volatile("ldmatrix.sync.aligned.m8n8.x4.shared.b16 {%0,%1,%2,%3}, [%4];"
                 : "=r"(r[0]), "=r"(r[1]), "=r"(r[2]), "=r"(r[3]) : "r"(addr));
}
__device__ __forceinline__ void cp_async16(unsigned int dst, const void* src) {
    asm volatile("cp.async.cg.shared.global [%0], [%1], 16;" :: "r"(dst), "l"(src));
}
__device__ __forceinline__ void cp_commit() {
    asm volatile("cp.async.commit_group;" ::: "memory");
}
__device__ __forceinline__ void cp_wait0() {
    asm volatile("cp.async.wait_group 0;" ::: "memory");
}

// ---------------- prep: pack W1 into fragment-ready bf16 hi/lo ----------------
__global__ void prep_w1(const float* __restrict__ W1) {
    int p = blockIdx.x * 256 + threadIdx.x;     // 0..16383 (s,T,lane)
    int l = p & 31;
    int T = (p >> 5) & 31;
    int s = p >> 10;
    int n  = T * 8 + (l >> 2);
    int kb = s * 16 + 2 * (l & 3);
#pragma unroll
    for (int q = 0; q < 2; q++) {
        int k = kb + q * 8;
        float v0 = W1[k * HIDDEN + n];
        float v1 = W1[(k + 1) * HIDDEN + n];
        float h0 = bf16hi_f(v0), h1 = bf16hi_f(v1);
        g_Bh[p * 2 + q] = pack_bf16x2(h0, h1);
        g_Bl[p * 2 + q] = pack_bf16x2(v0 - h0, v1 - h1);
    }
}

// ---------------- node logits ----------------
__global__ void node_kernel(const float* __restrict__ z,
                            const float* __restrict__ Wn,
                            const float* __restrict__ bn,
                            float* __restrict__ out, int n_nodes) {
    __shared__ float ws[LATENT * NTYPES];
    __shared__ float zs[32 * 132];
    __shared__ float bs[NTYPES];
    int tid = threadIdx.x;
    for (int idx = tid; idx < LATENT * NTYPES / 4; idx += THREADS)
        ((float4*)ws)[idx] = ((const float4*)Wn)[idx];
    if (tid < NTYPES) bs[tid] = bn[tid];
    long long nBase = (long long)blockIdx.x * 32;
    for (int idx = tid; idx < 32 * LATENT / 4; idx += THREADS) {
        int n = idx / (LATENT / 4), kk = idx % (LATENT / 4);
        long long gn = nBase + n;
        float4 v = make_float4(0.f, 0.f, 0.f, 0.f);
        if (gn < n_nodes) v = *(const float4*)(z + gn * LATENT + kk * 4);
        *(float4*)(zs + n * 132 + kk * 4) = v;
    }
    __syncthreads();
    int n = tid >> 3, tg = tid & 7;
    float a0 = bs[tg*4+0], a1 = bs[tg*4+1], a2 = bs[tg*4+2], a3 = bs[tg*4+3];
    const float* zr = zs + n * 132;
#pragma unroll 8
    for (int k = 0; k < LATENT; k++) {
        float zv = zr[k];
        float4 w = *(const float4*)(ws + k * NTYPES + tg * 4);
        a0 = fmaf(zv, w.x, a0); a1 = fmaf(zv, w.y, a1);
        a2 = fmaf(zv, w.z, a2); a3 = fmaf(zv, w.w, a3);
    }
    long long gn = nBase + n;
    if (gn < n_nodes)
        *(float4*)(out + gn * NTYPES + tg * 4) = make_float4(a0, a1, a2, a3);
}

// ---------------- edge kernel: bf16 mma.sync, hh+hl+lh split ----------------
__global__ void __launch_bounds__(THREADS, 1)
edge_kernel(const float* __restrict__ z,
            const int* __restrict__ ei,
            const float* __restrict__ b1,
            const float* __restrict__ W2,
            const float* __restrict__ b2,
            float* __restrict__ out,
            int n_edges, int n_nodes) {
    extern __shared__ char dsm[];
    __shared__ int   idx_r[E_TILE];
    __shared__ int   idx_c[E_TILE];
    __shared__ float w2s[ETYPES * W2STRIDE];
    __shared__ float b1s[HIDDEN];
    __shared__ float b2s[ETYPES];

    int tid  = threadIdx.x;
    int lane = tid & 31;
    int warp = tid >> 5;
    long long eBase = (long long)blockIdx.x * E_TILE;

    unsigned int smb = smem_u32(dsm);

    // ---- prefetch B chunk 0 (while we gather A)
    {
        unsigned int dst = smb + SM_B0;
        const uint4* sh = (const uint4*)g_Bh;           // chunk0 at offset 0
        const uint4* sl = (const uint4*)g_Bl;
#pragma unroll
        for (int u = 0; u < 8; u++) {
            cp_async16(dst + (tid + u * THREADS) * 16, sh + tid + u * THREADS);
            cp_async16(dst + 32768 + (tid + u * THREADS) * 16, sl + tid + u * THREADS);
        }
        cp_commit();
    }

    // ---- stage W2 / b1 / b2 / edge indices
    for (int idx = tid; idx < HIDDEN * ETYPES; idx += THREADS) {
        int k = idx / ETYPES, o = idx % ETYPES;
        w2s[o * W2STRIDE + k] = W2[idx];
    }
    if (tid < HIDDEN) b1s[tid] = b1[tid];
    if (tid < ETYPES) b2s[tid] = b2[tid];
    if (tid < E_TILE) {
        long long e = eBase + tid;
        if (e >= n_edges) e = n_edges - 1;
        int r = ei[e];
        int c = ei[(long long)n_edges + e];
        idx_r[tid] = min(max(r, 0), n_nodes - 1);
        idx_c[tid] = min(max(c, 0), n_nodes - 1);
    }
    __syncthreads();

    // ---- gather A: 64 edges x 256 k, bf16 hi/lo into ASTRIDE rows
    {
        int e_loc = tid >> 2;
        int quarter = tid & 3;                 // 64-k block
        int node = (quarter < 2) ? idx_r[e_loc] : idx_c[e_loc];
        const float* src = z + (long long)node * LATENT + (quarter & 1) * 64;
        unsigned short* Ah = (unsigned short*)dsm;
        unsigned short* Al = (unsigned short*)(dsm + SM_ALO);
        int base = e_loc * ASTRIDE + quarter * 64;
#pragma unroll
        for (int g = 0; g < 16; g++) {
            float4 v = *(const float4*)(src + g * 4);
            float h0 = bf16hi_f(v.x), h1 = bf16hi_f(v.y);
            float h2 = bf16hi_f(v.z), h3 = bf16hi_f(v.w);
            unsigned int* ph = (unsigned int*)(Ah + base + g * 4);
            unsigned int* pl = (unsigned int*)(Al + base + g * 4);
            ph[0] = pack_bf16x2(h0, h1);
            ph[1] = pack_bf16x2(h2, h3);
            pl[0] = pack_bf16x2(v.x - h0, v.y - h1);
            pl[1] = pack_bf16x2(v.z - h2, v.w - h3);
        }
    }

    // ---- mainloop
    float acc[4][4][4];
#pragma unroll
    for (int i = 0; i < 4; i++)
#pragma unroll
        for (int t = 0; t < 4; t++)
#pragma unroll
            for (int r = 0; r < 4; r++) acc[i][t][r] = 0.f;

    // ldmatrix source addresses (per lane), row = i*16 + (lane&15), col = (lane>>4)*8
    unsigned int a_row = (unsigned)(lane & 15);
    unsigned int a_col = (unsigned)((lane >> 4) * 8);

    for (int c = 0; c < NCHK; c++) {
        cp_wait0();
        __syncthreads();
        if (c + 1 < NCHK) {
            unsigned int dst = smb + SM_B0 + ((c + 1) & 1) * SM_BBYTES;
            const uint4* sh = (const uint4*)(g_Bh + (c + 1) * 8192);
            const uint4* sl = (const uint4*)(g_Bl + (c + 1) * 8192);
#pragma unroll
            for (int u = 0; u < 8; u++) {
                cp_async16(dst + (tid + u * THREADS) * 16, sh + tid + u * THREADS);
                cp_async16(dst + 32768 + (tid + u * THREADS) * 16, sl + tid + u * THREADS);
            }
            cp_commit();
        }

        unsigned int bbase = smb + SM_B0 + (c & 1) * SM_BBYTES;
#pragma unroll
        for (int s = 0; s < CHUNK_S; s++) {
            int k0 = c * 64 + s * 16;
            unsigned int ah[4][4], al[4][4];
#pragma unroll
            for (int i = 0; i < 4; i++) {
                unsigned int off = ((i * 16 + a_row) * ASTRIDE + k0 + a_col) * 2;
                ldmatrix4(ah[i], smb + off);
                ldmatrix4(al[i], smb + SM_ALO + off);
            }
#pragma unroll
            for (int t = 0; t < 4; t++) {
                int T = warp * 4 + t;
                unsigned int boff = bbase + (((unsigned)(s * 32 + T) * 32 + lane) * 8);
                unsigned int bh0, bh1, bl0, bl1;
                asm volatile("ld.shared.v2.u32 {%0,%1}, [%2];" : "=r"(bh0), "=r"(bh1) : "r"(boff));
                asm volatile("ld.shared.v2.u32 {%0,%1}, [%2];" : "=r"(bl0), "=r"(bl1) : "r"(boff + 32768));
#pragma unroll
                for (int i = 0; i < 4; i++) {
                    mma_bf16(acc[i][t], ah[i], bh0, bh1);   // hh
                    mma_bf16(acc[i][t], al[i], bh0, bh1);   // lh
                    mma_bf16(acc[i][t], ah[i], bl0, bl1);   // hl
                }
            }
        }
        __syncthreads();
    }

    // ---- epilogue: h = relu(acc + b1) into smem (overlay B region)
    __syncthreads();
    float* h = (float*)(dsm + SM_B0);
    int g   = lane >> 2;
    int tig = lane & 3;
#pragma unroll
    for (int i = 0; i < 4; i++) {
#pragma unroll
        for (int t = 0; t < 4; t++) {
            int n = warp * 32 + t * 8 + 2 * tig;
            int m0 = i * 16 + g;
            float bb0 = b1s[n], bb1 = b1s[n + 1];
            float2 v0 = make_float2(fmaxf(acc[i][t][0] + bb0, 0.f),
                                    fmaxf(acc[i][t][1] + bb1, 0.f));
            float2 v1 = make_float2(fmaxf(acc[i][t][2] + bb0, 0.f),
                                    fmaxf(acc[i][t][3] + bb1, 0.f));
            *(float2*)(h + m0 * HSTRIDE + n)       = v0;
            *(float2*)(h + (m0 + 8) * HSTRIDE + n) = v1;
        }
    }
    __syncthreads();

    // ---- GEMM2: h[64x256] @ W2[256x8] + b2
    int e0 = tid >> 3, o = tid & 7;
    float bo = b2s[o];
#pragma unroll
    for (int pass = 0; pass < 2; pass++) {
        int e = e0 + pass * 32;
        const float* hr = h + e * HSTRIDE;
        const float* wr = w2s + o * W2STRIDE;
        float a = bo;
#pragma unroll 8
        for (int k = 0; k < HIDDEN; k += 4) {
            float4 hv = *(const float4*)(hr + k);
            float4 wv = *(const float4*)(wr + k);
            a = fmaf(hv.x, wv.x, a);
            a = fmaf(hv.y, wv.y, a);
            a = fmaf(hv.z, wv.z, a);
            a = fmaf(hv.w, wv.w, a);
        }
        long long ge = eBase + e;
        if (ge < n_edges) out[ge * ETYPES + o] = a;
    }
}

// ---------------- launch ----------------
extern "C" void kernel_launch(void* const* d_in, const int* in_sizes, int n_in,
                              void* d_out, int out_size) {
    const float* z  = (const float*)d_in[0];
    const int*   ei = (const int*)d_in[1];
    const float* Wn = (const float*)d_in[2];
    const float* bn = (const float*)d_in[3];
    const float* W1 = (const float*)d_in[4];
    const float* b1 = (const float*)d_in[5];
    const float* W2 = (const float*)d_in[6];
    const float* b2 = (const float*)d_in[7];

    int n_nodes = in_sizes[0] / LATENT;
    int n_edges = in_sizes[1] / 2;
    float* out = (float*)d_out;

    prep_w1<<<64, 256>>>(W1);
    node_kernel<<<(n_nodes + 31) / 32, THREADS>>>(z, Wn, bn, out, n_nodes);

    cudaFuncSetAttribute(edge_kernel, cudaFuncAttributeMaxDynamicSharedMemorySize, DSMEM_BYTES);
    int grid = (n_edges + E_TILE - 1) / E_TILE;
    edge_kernel<<<grid, THREADS, DSMEM_BYTES>>>(
        z, ei, b1, W2, b2, out + (size_t)n_nodes * NTYPES, n_edges, n_nodes);
}

// round 7
// speedup vs baseline: 2.9477x; 1.5732x over previous
#include <cuda_runtime.h>
#include <cuda_fp16.h>
#include <cstdint>

#define LATENT   128
#define HIDDEN   256
#define NTYPES   32
#define ETYPES   8
#define E_TILE   64
#define THREADS  256
#define ASTRIDE  264          // fp16 elems per A row (pad: conflict-free ldmatrix)
#define HSTRIDE  264          // f32 elems per h row (epilogue overlay over A)
#define W2STRIDE 260
#define CHUNK_S  2            // k16-steps per B chunk
#define NCHK     8

// dynamic smem layout (bytes):
//  A_hi: 64*264*2 = 33792   @0
//  A_lo: 33792              @33792
//  Bbuf0: 16384             @67584
//  Bbuf1: 16384             @83968
//  h overlay (f32 64x264 = 67584) @0 after mainloop
#define SM_ALO    33792
#define SM_B0     67584
#define SM_BBYTES 16384
#define DSMEM_BYTES (67584 + 2 * 16384)

// fragment-ready packed W1 fp16, u32 words:
// word idx = (((s*32 + T)*32 + lane)*2 + q), s=k16 step, T=n8 tile, q=b0/b1
__device__ unsigned int g_B[32768];

__device__ __forceinline__ unsigned int smem_u32(const void* p) {
    unsigned int a;
    asm("{ .reg .u64 t; cvta.to.shared.u64 t, %1; cvt.u32.u64 %0, t; }" : "=r"(a) : "l"(p));
    return a;
}
__device__ __forceinline__ unsigned int pack_h2(__half a, __half b) {
    __half2 h = __halves2half2(a, b);
    return *reinterpret_cast<unsigned int*>(&h);
}
__device__ __forceinline__ void mma_f16(float* c, const unsigned int* a,
                                        unsigned int b0, unsigned int b1) {
    asm volatile(
        "mma.sync.aligned.m16n8k16.row.col.f32.f16.f16.f32 "
        "{%0,%1,%2,%3}, {%4,%5,%6,%7}, {%8,%9}, {%0,%1,%2,%3};"
        : "+f"(c[0]), "+f"(c[1]), "+f"(c[2]), "+f"(c[3])
        : "r"(a[0]), "r"(a[1]), "r"(a[2]), "r"(a[3]), "r"(b0), "r"(b1));
}
__device__ __forceinline__ void ldmatrix4(unsigned int* r, unsigned int addr) {
    asm volatile("ldmatrix.sync.aligned.m8n8.x4.shared.b16 {%0,%1,%2,%3}, [%4];"
                 : "=r"(r[0]), "=r"(r[1]), "=r"(r[2]), "=r"(r[3]) : "r"(addr));
}
__device__ __forceinline__ void cp_async16(unsigned int dst, const void* src) {
    asm volatile("cp.async.cg.shared.global [%0], [%1], 16;" :: "r"(dst), "l"(src));
}
__device__ __forceinline__ void cp_commit() {
    asm volatile("cp.async.commit_group;" ::: "memory");
}
__device__ __forceinline__ void cp_wait0() {
    asm volatile("cp.async.wait_group 0;" ::: "memory");
}

// ---------------- prep: pack W1 into fragment-ready fp16 ----------------
__global__ void prep_w1(const float* __restrict__ W1) {
    int p = blockIdx.x * 256 + threadIdx.x;     // 0..16383 (s,T,lane)
    int l = p & 31;
    int T = (p >> 5) & 31;
    int s = p >> 10;
    int n  = T * 8 + (l >> 2);
    int kb = s * 16 + 2 * (l & 3);
#pragma unroll
    for (int q = 0; q < 2; q++) {
        int k = kb + q * 8;
        __half h0 = __float2half_rn(W1[k * HIDDEN + n]);
        __half h1 = __float2half_rn(W1[(k + 1) * HIDDEN + n]);
        g_B[p * 2 + q] = pack_h2(h0, h1);
    }
}

// ---------------- node logits ----------------
__global__ void node_kernel(const float* __restrict__ z,
                            const float* __restrict__ Wn,
                            const float* __restrict__ bn,
                            float* __restrict__ out, int n_nodes) {
    __shared__ float ws[LATENT * NTYPES];
    __shared__ float zs[32 * 132];
    __shared__ float bs[NTYPES];
    int tid = threadIdx.x;
    for (int idx = tid; idx < LATENT * NTYPES / 4; idx += THREADS)
        ((float4*)ws)[idx] = ((const float4*)Wn)[idx];
    if (tid < NTYPES) bs[tid] = bn[tid];
    long long nBase = (long long)blockIdx.x * 32;
    for (int idx = tid; idx < 32 * LATENT / 4; idx += THREADS) {
        int n = idx / (LATENT / 4), kk = idx % (LATENT / 4);
        long long gn = nBase + n;
        float4 v = make_float4(0.f, 0.f, 0.f, 0.f);
        if (gn < n_nodes) v = *(const float4*)(z + gn * LATENT + kk * 4);
        *(float4*)(zs + n * 132 + kk * 4) = v;
    }
    __syncthreads();
    int n = tid >> 3, tg = tid & 7;
    float a0 = bs[tg*4+0], a1 = bs[tg*4+1], a2 = bs[tg*4+2], a3 = bs[tg*4+3];
    const float* zr = zs + n * 132;
#pragma unroll 8
    for (int k = 0; k < LATENT; k++) {
        float zv = zr[k];
        float4 w = *(const float4*)(ws + k * NTYPES + tg * 4);
        a0 = fmaf(zv, w.x, a0); a1 = fmaf(zv, w.y, a1);
        a2 = fmaf(zv, w.z, a2); a3 = fmaf(zv, w.w, a3);
    }
    long long gn = nBase + n;
    if (gn < n_nodes)
        *(float4*)(out + gn * NTYPES + tg * 4) = make_float4(a0, a1, a2, a3);
}

// ---------------- edge kernel: fp16 mma.sync, (Ah+Al) x Bh 2-term ----------------
__global__ void __launch_bounds__(THREADS, 2)
edge_kernel(const float* __restrict__ z,
            const int* __restrict__ ei,
            const float* __restrict__ b1,
            const float* __restrict__ W2,
            const float* __restrict__ b2,
            float* __restrict__ out,
            int n_edges, int n_nodes) {
    extern __shared__ char dsm[];
    __shared__ int   idx_r[E_TILE];
    __shared__ int   idx_c[E_TILE];
    __shared__ float w2s[ETYPES * W2STRIDE];
    __shared__ float b1s[HIDDEN];
    __shared__ float b2s[ETYPES];

    int tid  = threadIdx.x;
    int lane = tid & 31;
    int warp = tid >> 5;
    long long eBase = (long long)blockIdx.x * E_TILE;

    unsigned int smb = smem_u32(dsm);

    // ---- prefetch B chunk 0 (16 KB = 1024 uint4)
    {
        unsigned int dst = smb + SM_B0;
        const uint4* sb = (const uint4*)g_B;
#pragma unroll
        for (int u = 0; u < 4; u++)
            cp_async16(dst + (tid + u * THREADS) * 16, sb + tid + u * THREADS);
        cp_commit();
    }

    // ---- stage W2 / b1 / b2 / edge indices
    for (int idx = tid; idx < HIDDEN * ETYPES; idx += THREADS) {
        int k = idx / ETYPES, o = idx % ETYPES;
        w2s[o * W2STRIDE + k] = W2[idx];
    }
    if (tid < HIDDEN) b1s[tid] = b1[tid];
    if (tid < ETYPES) b2s[tid] = b2[tid];
    if (tid < E_TILE) {
        long long e = eBase + tid;
        if (e >= n_edges) e = n_edges - 1;
        int r = ei[e];
        int c = ei[(long long)n_edges + e];
        idx_r[tid] = min(max(r, 0), n_nodes - 1);
        idx_c[tid] = min(max(c, 0), n_nodes - 1);
    }
    __syncthreads();

    // ---- gather A: 64 edges x 256 k, fp16 hi + fp16 residual
    {
        int e_loc = tid >> 2;
        int quarter = tid & 3;
        int node = (quarter < 2) ? idx_r[e_loc] : idx_c[e_loc];
        const float* src = z + (long long)node * LATENT + (quarter & 1) * 64;
        unsigned short* Ah = (unsigned short*)dsm;
        unsigned short* Al = (unsigned short*)(dsm + SM_ALO);
        int base = e_loc * ASTRIDE + quarter * 64;
#pragma unroll
        for (int g = 0; g < 16; g++) {
            float4 v = *(const float4*)(src + g * 4);
            __half h0 = __float2half_rn(v.x), h1 = __float2half_rn(v.y);
            __half h2 = __float2half_rn(v.z), h3 = __float2half_rn(v.w);
            __half l0 = __float2half_rn(v.x - __half2float(h0));
            __half l1 = __float2half_rn(v.y - __half2float(h1));
            __half l2 = __float2half_rn(v.z - __half2float(h2));
            __half l3 = __float2half_rn(v.w - __half2float(h3));
            unsigned int* ph = (unsigned int*)(Ah + base + g * 4);
            unsigned int* pl = (unsigned int*)(Al + base + g * 4);
            ph[0] = pack_h2(h0, h1);
            ph[1] = pack_h2(h2, h3);
            pl[0] = pack_h2(l0, l1);
            pl[1] = pack_h2(l2, l3);
        }
    }

    // ---- mainloop
    float acc[4][4][4];
#pragma unroll
    for (int i = 0; i < 4; i++)
#pragma unroll
        for (int t = 0; t < 4; t++)
#pragma unroll
            for (int r = 0; r < 4; r++) acc[i][t][r] = 0.f;

    unsigned int a_row = (unsigned)(lane & 15);
    unsigned int a_col = (unsigned)((lane >> 4) * 8);

    for (int c = 0; c < NCHK; c++) {
        cp_wait0();
        __syncthreads();
        if (c + 1 < NCHK) {
            unsigned int dst = smb + SM_B0 + ((c + 1) & 1) * SM_BBYTES;
            const uint4* sb = (const uint4*)(g_B + (c + 1) * 4096);
#pragma unroll
            for (int u = 0; u < 4; u++)
                cp_async16(dst + (tid + u * THREADS) * 16, sb + tid + u * THREADS);
            cp_commit();
        }

        unsigned int bbase = smb + SM_B0 + (c & 1) * SM_BBYTES;
#pragma unroll
        for (int s = 0; s < CHUNK_S; s++) {
            int k0 = (c * CHUNK_S + s) * 16;
            // load all 4 B fragments for this step (this warp's T tiles)
            unsigned int bw[4][2];
#pragma unroll
            for (int t = 0; t < 4; t++) {
                int T = warp * 4 + t;
                unsigned int boff = bbase + (((unsigned)(s * 32 + T) * 32 + lane) * 8);
                asm volatile("ld.shared.v2.u32 {%0,%1}, [%2];"
                             : "=r"(bw[t][0]), "=r"(bw[t][1]) : "r"(boff));
            }
#pragma unroll
            for (int i = 0; i < 4; i++) {
                unsigned int ah[4], al[4];
                unsigned int off = ((i * 16 + a_row) * ASTRIDE + k0 + a_col) * 2;
                ldmatrix4(ah, smb + off);
                ldmatrix4(al, smb + SM_ALO + off);
#pragma unroll
                for (int t = 0; t < 4; t++) {
                    mma_f16(acc[i][t], ah, bw[t][0], bw[t][1]);
                    mma_f16(acc[i][t], al, bw[t][0], bw[t][1]);
                }
            }
        }
        __syncthreads();
    }

    // ---- epilogue: h = relu(acc + b1) into smem (overlay A region)
    __syncthreads();
    float* h = (float*)dsm;
    int g   = lane >> 2;
    int tig = lane & 3;
#pragma unroll
    for (int i = 0; i < 4; i++) {
#pragma unroll
        for (int t = 0; t < 4; t++) {
            int n = warp * 32 + t * 8 + 2 * tig;
            int m0 = i * 16 + g;
            float bb0 = b1s[n], bb1 = b1s[n + 1];
            float2 v0 = make_float2(fmaxf(acc[i][t][0] + bb0, 0.f),
                                    fmaxf(acc[i][t][1] + bb1, 0.f));
            float2 v1 = make_float2(fmaxf(acc[i][t][2] + bb0, 0.f),
                                    fmaxf(acc[i][t][3] + bb1, 0.f));
            *(float2*)(h + m0 * HSTRIDE + n)       = v0;
            *(float2*)(h + (m0 + 8) * HSTRIDE + n) = v1;
        }
    }
    __syncthreads();

    // ---- GEMM2: h[64x256] @ W2[256x8] + b2
    int e0 = tid >> 3, o = tid & 7;
    float bo = b2s[o];
#pragma unroll
    for (int pass = 0; pass < 2; pass++) {
        int e = e0 + pass * 32;
        const float* hr = h + e * HSTRIDE;
        const float* wr = w2s + o * W2STRIDE;
        float a = bo;
#pragma unroll 8
        for (int k = 0; k < HIDDEN; k += 4) {
            float4 hv = *(const float4*)(hr + k);
            float4 wv = *(const float4*)(wr + k);
            a = fmaf(hv.x, wv.x, a);
            a = fmaf(hv.y, wv.y, a);
            a = fmaf(hv.z, wv.z, a);
            a = fmaf(hv.w, wv.w, a);
        }
        long long ge = eBase + e;
        if (ge < n_edges) out[ge * ETYPES + o] = a;
    }
}

// ---------------- launch ----------------
extern "C" void kernel_launch(void* const* d_in, const int* in_sizes, int n_in,
                              void* d_out, int out_size) {
    const float* z  = (const float*)d_in[0];
    const int*   ei = (const int*)d_in[1];
    const float* Wn = (const float*)d_in[2];
    const float* bn = (const float*)d_in[3];
    const float* W1 = (const float*)d_in[4];
    const float* b1 = (const float*)d_in[5];
    const float* W2 = (const float*)d_in[6];
    const float* b2 = (const float*)d_in[7];

    int n_nodes = in_sizes[0] / LATENT;
    int n_edges = in_sizes[1] / 2;
    float* out = (float*)d_out;

    prep_w1<<<64, 256>>>(W1);
    node_kernel<<<(n_nodes + 31) / 32, THREADS>>>(z, Wn, bn, out, n_nodes);

    cudaFuncSetAttribute(edge_kernel, cudaFuncAttributeMaxDynamicSharedMemorySize, DSMEM_BYTES);
    int grid = (n_edges + E_TILE - 1) / E_TILE;
    edge_kernel<<<grid, THREADS, DSMEM_BYTES>>>(
        z, ei, b1, W2, b2, out + (size_t)n_nodes * NTYPES, n_edges, n_nodes);
}

// round 8
// speedup vs baseline: 2.9498x; 1.0007x over previous
#include <cuda_runtime.h>
#include <cuda_fp16.h>
#include <cstdint>

#define LATENT   128
#define HIDDEN   256
#define NTYPES   32
#define ETYPES   8
#define E_TILE   64
#define THREADS  256
#define ASTRIDE  264          // fp16 elems per A row (pad: conflict-free ldmatrix)
#define HSTRIDE  264          // f32 elems per h row (epilogue overlay over A)
#define W2STRIDE 260
#define CHUNK_S  2            // k16-steps per B chunk
#define NCHK     8

#define SM_ALO    33792
#define SM_B0     67584
#define SM_BBYTES 16384
#define DSMEM_BYTES (67584 + 2 * 16384)

// fragment-ready packed W1 fp16, u32 words:
// word idx = (((s*32 + T)*32 + lane)*2 + q), s=k16 step, T=n8 tile, q=b0/b1
__device__ unsigned int g_B[32768];

__device__ __forceinline__ unsigned int smem_u32(const void* p) {
    unsigned int a;
    asm("{ .reg .u64 t; cvta.to.shared.u64 t, %1; cvt.u32.u64 %0, t; }" : "=r"(a) : "l"(p));
    return a;
}
__device__ __forceinline__ unsigned int pack_h2(__half a, __half b) {
    __half2 h = __halves2half2(a, b);
    return *reinterpret_cast<unsigned int*>(&h);
}
__device__ __forceinline__ void mma_f16(float* c, const unsigned int* a,
                                        unsigned int b0, unsigned int b1) {
    asm volatile(
        "mma.sync.aligned.m16n8k16.row.col.f32.f16.f16.f32 "
        "{%0,%1,%2,%3}, {%4,%5,%6,%7}, {%8,%9}, {%0,%1,%2,%3};"
        : "+f"(c[0]), "+f"(c[1]), "+f"(c[2]), "+f"(c[3])
        : "r"(a[0]), "r"(a[1]), "r"(a[2]), "r"(a[3]), "r"(b0), "r"(b1));
}
__device__ __forceinline__ void ldmatrix4(unsigned int* r, unsigned int addr) {
    asm volatile("ldmatrix.sync.aligned.m8n8.x4.shared.b16 {%0,%1,%2,%3}, [%4];"
                 : "=r"(r[0]), "=r"(r[1]), "=r"(r[2]), "=r"(r[3]) : "r"(addr));
}
__device__ __forceinline__ void cp_async16(unsigned int dst, const void* src) {
    asm volatile("cp.async.cg.shared.global [%0], [%1], 16;" :: "r"(dst), "l"(src));
}
__device__ __forceinline__ void cp_commit() {
    asm volatile("cp.async.commit_group;" ::: "memory");
}
__device__ __forceinline__ void cp_wait0() {
    asm volatile("cp.async.wait_group 0;" ::: "memory");
}

// ---------------- prep: pack W1 into fragment-ready fp16 ----------------
__global__ void prep_w1(const float* __restrict__ W1) {
    int p = blockIdx.x * 256 + threadIdx.x;     // 0..16383 (s,T,lane)
    int l = p & 31;
    int T = (p >> 5) & 31;
    int s = p >> 10;
    int n  = T * 8 + (l >> 2);
    int kb = s * 16 + 2 * (l & 3);
#pragma unroll
    for (int q = 0; q < 2; q++) {
        int k = kb + q * 8;
        __half h0 = __float2half_rn(W1[k * HIDDEN + n]);
        __half h1 = __float2half_rn(W1[(k + 1) * HIDDEN + n]);
        g_B[p * 2 + q] = pack_h2(h0, h1);
    }
}

// ---------------- node logits ----------------
__global__ void node_kernel(const float* __restrict__ z,
                            const float* __restrict__ Wn,
                            const float* __restrict__ bn,
                            float* __restrict__ out, int n_nodes) {
    __shared__ float ws[LATENT * NTYPES];
    __shared__ float zs[32 * 132];
    __shared__ float bs[NTYPES];
    int tid = threadIdx.x;
    for (int idx = tid; idx < LATENT * NTYPES / 4; idx += THREADS)
        ((float4*)ws)[idx] = ((const float4*)Wn)[idx];
    if (tid < NTYPES) bs[tid] = bn[tid];
    long long nBase = (long long)blockIdx.x * 32;
    for (int idx = tid; idx < 32 * LATENT / 4; idx += THREADS) {
        int n = idx / (LATENT / 4), kk = idx % (LATENT / 4);
        long long gn = nBase + n;
        float4 v = make_float4(0.f, 0.f, 0.f, 0.f);
        if (gn < n_nodes) v = *(const float4*)(z + gn * LATENT + kk * 4);
        *(float4*)(zs + n * 132 + kk * 4) = v;
    }
    __syncthreads();
    int n = tid >> 3, tg = tid & 7;
    float a0 = bs[tg*4+0], a1 = bs[tg*4+1], a2 = bs[tg*4+2], a3 = bs[tg*4+3];
    const float* zr = zs + n * 132;
#pragma unroll 8
    for (int k = 0; k < LATENT; k++) {
        float zv = zr[k];
        float4 w = *(const float4*)(ws + k * NTYPES + tg * 4);
        a0 = fmaf(zv, w.x, a0); a1 = fmaf(zv, w.y, a1);
        a2 = fmaf(zv, w.z, a2); a3 = fmaf(zv, w.w, a3);
    }
    long long gn = nBase + n;
    if (gn < n_nodes)
        *(float4*)(out + gn * NTYPES + tg * 4) = make_float4(a0, a1, a2, a3);
}

// ---------------- edge kernel: fp16 mma.sync, (Ah+Al) x B, stall-free order ----
__global__ void __launch_bounds__(THREADS, 2)
edge_kernel(const float* __restrict__ z,
            const int* __restrict__ ei,
            const float* __restrict__ b1,
            const float* __restrict__ W2,
            const float* __restrict__ b2,
            float* __restrict__ out,
            int n_edges, int n_nodes) {
    extern __shared__ char dsm[];
    __shared__ int   idx_r[E_TILE];
    __shared__ int   idx_c[E_TILE];
    __shared__ float w2s[ETYPES * W2STRIDE];
    __shared__ float b1s[HIDDEN];
    __shared__ float b2s[ETYPES];

    int tid  = threadIdx.x;
    int lane = tid & 31;
    int warp = tid >> 5;
    long long eBase = (long long)blockIdx.x * E_TILE;

    unsigned int smb = smem_u32(dsm);

    // ---- prefetch B chunk 0
    {
        unsigned int dst = smb + SM_B0;
        const uint4* sb = (const uint4*)g_B;
#pragma unroll
        for (int u = 0; u < 4; u++)
            cp_async16(dst + (tid + u * THREADS) * 16, sb + tid + u * THREADS);
        cp_commit();
    }

    // ---- stage W2 / b1 / b2 / edge indices
    for (int idx = tid; idx < HIDDEN * ETYPES; idx += THREADS) {
        int k = idx / ETYPES, o = idx % ETYPES;
        w2s[o * W2STRIDE + k] = W2[idx];
    }
    if (tid < HIDDEN) b1s[tid] = b1[tid];
    if (tid < ETYPES) b2s[tid] = b2[tid];
    if (tid < E_TILE) {
        long long e = eBase + tid;
        if (e >= n_edges) e = n_edges - 1;
        int r = ei[e];
        int c = ei[(long long)n_edges + e];
        idx_r[tid] = min(max(r, 0), n_nodes - 1);
        idx_c[tid] = min(max(c, 0), n_nodes - 1);
    }
    __syncthreads();

    // ---- gather A: 64 edges x 256 k, fp16 hi + fp16 residual
    {
        int e_loc = tid >> 2;
        int quarter = tid & 3;
        int node = (quarter < 2) ? idx_r[e_loc] : idx_c[e_loc];
        const float* src = z + (long long)node * LATENT + (quarter & 1) * 64;
        unsigned short* Ah = (unsigned short*)dsm;
        unsigned short* Al = (unsigned short*)(dsm + SM_ALO);
        int base = e_loc * ASTRIDE + quarter * 64;
#pragma unroll
        for (int g = 0; g < 16; g++) {
            float4 v = *(const float4*)(src + g * 4);
            __half h0 = __float2half_rn(v.x), h1 = __float2half_rn(v.y);
            __half h2 = __float2half_rn(v.z), h3 = __float2half_rn(v.w);
            __half l0 = __float2half_rn(v.x - __half2float(h0));
            __half l1 = __float2half_rn(v.y - __half2float(h1));
            __half l2 = __float2half_rn(v.z - __half2float(h2));
            __half l3 = __float2half_rn(v.w - __half2float(h3));
            unsigned int* ph = (unsigned int*)(Ah + base + g * 4);
            unsigned int* pl = (unsigned int*)(Al + base + g * 4);
            ph[0] = pack_h2(h0, h1);
            ph[1] = pack_h2(h2, h3);
            pl[0] = pack_h2(l0, l1);
            pl[1] = pack_h2(l2, l3);
        }
    }

    // ---- mainloop
    float acc[4][4][4];
#pragma unroll
    for (int i = 0; i < 4; i++)
#pragma unroll
        for (int t = 0; t < 4; t++)
#pragma unroll
            for (int r = 0; r < 4; r++) acc[i][t][r] = 0.f;

    unsigned int a_row = (unsigned)(lane & 15);
    unsigned int a_col = (unsigned)((lane >> 4) * 8);

    for (int c = 0; c < NCHK; c++) {
        cp_wait0();
        __syncthreads();
        if (c + 1 < NCHK) {
            unsigned int dst = smb + SM_B0 + ((c + 1) & 1) * SM_BBYTES;
            const uint4* sb = (const uint4*)(g_B + (c + 1) * 4096);
#pragma unroll
            for (int u = 0; u < 4; u++)
                cp_async16(dst + (tid + u * THREADS) * 16, sb + tid + u * THREADS);
            cp_commit();
        }

        unsigned int bbase = smb + SM_B0 + (c & 1) * SM_BBYTES;
#pragma unroll
        for (int s = 0; s < CHUNK_S; s++) {
            int k0 = (c * CHUNK_S + s) * 16;
            unsigned int bw[4][2];
#pragma unroll
            for (int t = 0; t < 4; t++) {
                int T = warp * 4 + t;
                unsigned int boff = bbase + (((unsigned)(s * 32 + T) * 32 + lane) * 8);
                asm volatile("ld.shared.v2.u32 {%0,%1}, [%2];"
                             : "=r"(bw[t][0]), "=r"(bw[t][1]) : "r"(boff));
            }
#pragma unroll
            for (int i = 0; i < 4; i++) {
                unsigned int ah[4], al[4];
                unsigned int off = ((i * 16 + a_row) * ASTRIDE + k0 + a_col) * 2;
                ldmatrix4(ah, smb + off);
                ldmatrix4(al, smb + SM_ALO + off);
                // pass 1: all hi MMAs (independent accumulators, no RAW pairs)
#pragma unroll
                for (int t = 0; t < 4; t++)
                    mma_f16(acc[i][t], ah, bw[t][0], bw[t][1]);
                // pass 2: all lo MMAs (same acc reused at distance 4)
#pragma unroll
                for (int t = 0; t < 4; t++)
                    mma_f16(acc[i][t], al, bw[t][0], bw[t][1]);
            }
        }
        __syncthreads();
    }

    // ---- epilogue: h = relu(acc + b1) into smem (overlay A region)
    __syncthreads();
    float* h = (float*)dsm;
    int g   = lane >> 2;
    int tig = lane & 3;
#pragma unroll
    for (int i = 0; i < 4; i++) {
#pragma unroll
        for (int t = 0; t < 4; t++) {
            int n = warp * 32 + t * 8 + 2 * tig;
            int m0 = i * 16 + g;
            float bb0 = b1s[n], bb1 = b1s[n + 1];
            float2 v0 = make_float2(fmaxf(acc[i][t][0] + bb0, 0.f),
                                    fmaxf(acc[i][t][1] + bb1, 0.f));
            float2 v1 = make_float2(fmaxf(acc[i][t][2] + bb0, 0.f),
                                    fmaxf(acc[i][t][3] + bb1, 0.f));
            *(float2*)(h + m0 * HSTRIDE + n)       = v0;
            *(float2*)(h + (m0 + 8) * HSTRIDE + n) = v1;
        }
    }
    __syncthreads();

    // ---- GEMM2: h[64x256] @ W2[256x8] + b2
    int e0 = tid >> 3, o = tid & 7;
    float bo = b2s[o];
#pragma unroll
    for (int pass = 0; pass < 2; pass++) {
        int e = e0 + pass * 32;
        const float* hr = h + e * HSTRIDE;
        const float* wr = w2s + o * W2STRIDE;
        float a = bo;
#pragma unroll 8
        for (int k = 0; k < HIDDEN; k += 4) {
            float4 hv = *(const float4*)(hr + k);
            float4 wv = *(const float4*)(wr + k);
            a = fmaf(hv.x, wv.x, a);
            a = fmaf(hv.y, wv.y, a);
            a = fmaf(hv.z, wv.z, a);
            a = fmaf(hv.w, wv.w, a);
        }
        long long ge = eBase + e;
        if (ge < n_edges) out[ge * ETYPES + o] = a;
    }
}

// ---------------- launch ----------------
extern "C" void kernel_launch(void* const* d_in, const int* in_sizes, int n_in,
                              void* d_out, int out_size) {
    const float* z  = (const float*)d_in[0];
    const int*   ei = (const int*)d_in[1];
    const float* Wn = (const float*)d_in[2];
    const float* bn = (const float*)d_in[3];
    const float* W1 = (const float*)d_in[4];
    const float* b1 = (const float*)d_in[5];
    const float* W2 = (const float*)d_in[6];
    const float* b2 = (const float*)d_in[7];

    int n_nodes = in_sizes[0] / LATENT;
    int n_edges = in_sizes[1] / 2;
    float* out = (float*)d_out;

    prep_w1<<<64, 256>>>(W1);
    node_kernel<<<(n_nodes + 31) / 32, THREADS>>>(z, Wn, bn, out, n_nodes);

    cudaFuncSetAttribute(edge_kernel, cudaFuncAttributeMaxDynamicSharedMemorySize, DSMEM_BYTES);
    int grid = (n_edges + E_TILE - 1) / E_TILE;
    edge_kernel<<<grid, THREADS, DSMEM_BYTES>>>(
        z, ei, b1, W2, b2, out + (size_t)n_nodes * NTYPES, n_edges, n_nodes);
}

// round 9
// speedup vs baseline: 4.3215x; 1.4650x over previous
#include <cuda_runtime.h>
#include <cuda_fp16.h>
#include <cstdint>

#define LATENT   128
#define HIDDEN   256
#define NTYPES   32
#define ETYPES   8
#define E_TILE   64
#define THREADS  256
#define ASTRIDE  264          // fp16 elems per A row (pad: conflict-free ldmatrix)
#define W2STRIDE 260
#define CHUNK_S  2            // k16-steps per B chunk
#define NCHK     8

// dynamic smem layout (bytes):
//  A: 64*264*2 = 33792      @0   (h overlay fp16 64x264 after mainloop)
//  Bbuf0: 16384             @33792
//  Bbuf1: 16384             @50176
#define SM_B0     33792
#define SM_BBYTES 16384
#define DSMEM_BYTES (33792 + 2 * 16384)

__device__ unsigned int g_B[32768];

__device__ __forceinline__ unsigned int smem_u32(const void* p) {
    unsigned int a;
    asm("{ .reg .u64 t; cvta.to.shared.u64 t, %1; cvt.u32.u64 %0, t; }" : "=r"(a) : "l"(p));
    return a;
}
__device__ __forceinline__ unsigned int pack_h2(__half a, __half b) {
    __half2 h = __halves2half2(a, b);
    return *reinterpret_cast<unsigned int*>(&h);
}
__device__ __forceinline__ void mma_f16(float* c, const unsigned int* a,
                                        unsigned int b0, unsigned int b1) {
    asm volatile(
        "mma.sync.aligned.m16n8k16.row.col.f32.f16.f16.f32 "
        "{%0,%1,%2,%3}, {%4,%5,%6,%7}, {%8,%9}, {%0,%1,%2,%3};"
        : "+f"(c[0]), "+f"(c[1]), "+f"(c[2]), "+f"(c[3])
        : "r"(a[0]), "r"(a[1]), "r"(a[2]), "r"(a[3]), "r"(b0), "r"(b1));
}
__device__ __forceinline__ void ldmatrix4(unsigned int* r, unsigned int addr) {
    asm volatile("ldmatrix.sync.aligned.m8n8.x4.shared.b16 {%0,%1,%2,%3}, [%4];"
                 : "=r"(r[0]), "=r"(r[1]), "=r"(r[2]), "=r"(r[3]) : "r"(addr));
}
__device__ __forceinline__ void cp_async16(unsigned int dst, const void* src) {
    asm volatile("cp.async.cg.shared.global [%0], [%1], 16;" :: "r"(dst), "l"(src));
}
__device__ __forceinline__ void cp_commit() {
    asm volatile("cp.async.commit_group;" ::: "memory");
}
__device__ __forceinline__ void cp_wait0() {
    asm volatile("cp.async.wait_group 0;" ::: "memory");
}

// ---------------- prep: pack W1 into fragment-ready fp16 ----------------
__global__ void prep_w1(const float* __restrict__ W1) {
    int p = blockIdx.x * 256 + threadIdx.x;
    int l = p & 31;
    int T = (p >> 5) & 31;
    int s = p >> 10;
    int n  = T * 8 + (l >> 2);
    int kb = s * 16 + 2 * (l & 3);
#pragma unroll
    for (int q = 0; q < 2; q++) {
        int k = kb + q * 8;
        __half h0 = __float2half_rn(W1[k * HIDDEN + n]);
        __half h1 = __float2half_rn(W1[(k + 1) * HIDDEN + n]);
        g_B[p * 2 + q] = pack_h2(h0, h1);
    }
}

// ---------------- node logits ----------------
__global__ void node_kernel(const float* __restrict__ z,
                            const float* __restrict__ Wn,
                            const float* __restrict__ bn,
                            float* __restrict__ out, int n_nodes) {
    __shared__ float ws[LATENT * NTYPES];
    __shared__ float zs[32 * 132];
    __shared__ float bs[NTYPES];
    int tid = threadIdx.x;
    for (int idx = tid; idx < LATENT * NTYPES / 4; idx += THREADS)
        ((float4*)ws)[idx] = ((const float4*)Wn)[idx];
    if (tid < NTYPES) bs[tid] = bn[tid];
    long long nBase = (long long)blockIdx.x * 32;
    for (int idx = tid; idx < 32 * LATENT / 4; idx += THREADS) {
        int n = idx / (LATENT / 4), kk = idx % (LATENT / 4);
        long long gn = nBase + n;
        float4 v = make_float4(0.f, 0.f, 0.f, 0.f);
        if (gn < n_nodes) v = *(const float4*)(z + gn * LATENT + kk * 4);
        *(float4*)(zs + n * 132 + kk * 4) = v;
    }
    __syncthreads();
    int n = tid >> 3, tg = tid & 7;
    float a0 = bs[tg*4+0], a1 = bs[tg*4+1], a2 = bs[tg*4+2], a3 = bs[tg*4+3];
    const float* zr = zs + n * 132;
#pragma unroll 8
    for (int k = 0; k < LATENT; k++) {
        float zv = zr[k];
        float4 w = *(const float4*)(ws + k * NTYPES + tg * 4);
        a0 = fmaf(zv, w.x, a0); a1 = fmaf(zv, w.y, a1);
        a2 = fmaf(zv, w.z, a2); a3 = fmaf(zv, w.w, a3);
    }
    long long gn = nBase + n;
    if (gn < n_nodes)
        *(float4*)(out + gn * NTYPES + tg * 4) = make_float4(a0, a1, a2, a3);
}

// ---------------- edge kernel: single-term fp16 mma.sync ----------------
__global__ void __launch_bounds__(THREADS, 2)
edge_kernel(const float* __restrict__ z,
            const int* __restrict__ ei,
            const float* __restrict__ b1,
            const float* __restrict__ W2,
            const float* __restrict__ b2,
            float* __restrict__ out,
            int n_edges, int n_nodes) {
    extern __shared__ char dsm[];
    __shared__ int   idx_r[E_TILE];
    __shared__ int   idx_c[E_TILE];
    __shared__ float w2s[ETYPES * W2STRIDE];
    __shared__ float b1s[HIDDEN];
    __shared__ float b2s[ETYPES];

    int tid  = threadIdx.x;
    int lane = tid & 31;
    int warp = tid >> 5;
    long long eBase = (long long)blockIdx.x * E_TILE;

    unsigned int smb = smem_u32(dsm);

    // ---- prefetch B chunk 0
    {
        unsigned int dst = smb + SM_B0;
        const uint4* sb = (const uint4*)g_B;
#pragma unroll
        for (int u = 0; u < 4; u++)
            cp_async16(dst + (tid + u * THREADS) * 16, sb + tid + u * THREADS);
        cp_commit();
    }

    // ---- stage W2 / b1 / b2 / edge indices
    for (int idx = tid; idx < HIDDEN * ETYPES; idx += THREADS) {
        int k = idx / ETYPES, o = idx % ETYPES;
        w2s[o * W2STRIDE + k] = W2[idx];
    }
    if (tid < HIDDEN) b1s[tid] = b1[tid];
    if (tid < ETYPES) b2s[tid] = b2[tid];
    if (tid < E_TILE) {
        long long e = eBase + tid;
        if (e >= n_edges) e = n_edges - 1;
        int r = ei[e];
        int c = ei[(long long)n_edges + e];
        idx_r[tid] = min(max(r, 0), n_nodes - 1);
        idx_c[tid] = min(max(c, 0), n_nodes - 1);
    }
    __syncthreads();

    // ---- gather A: 64 edges x 256 k, fp16
    {
        int e_loc = tid >> 2;
        int quarter = tid & 3;
        int node = (quarter < 2) ? idx_r[e_loc] : idx_c[e_loc];
        const float* src = z + (long long)node * LATENT + (quarter & 1) * 64;
        unsigned short* Ah = (unsigned short*)dsm;
        int base = e_loc * ASTRIDE + quarter * 64;
#pragma unroll
        for (int g = 0; g < 16; g++) {
            float4 v = *(const float4*)(src + g * 4);
            unsigned int* ph = (unsigned int*)(Ah + base + g * 4);
            ph[0] = pack_h2(__float2half_rn(v.x), __float2half_rn(v.y));
            ph[1] = pack_h2(__float2half_rn(v.z), __float2half_rn(v.w));
        }
    }

    // ---- mainloop
    float acc[4][4][4];
#pragma unroll
    for (int i = 0; i < 4; i++)
#pragma unroll
        for (int t = 0; t < 4; t++)
#pragma unroll
            for (int r = 0; r < 4; r++) acc[i][t][r] = 0.f;

    unsigned int a_row = (unsigned)(lane & 15);
    unsigned int a_col = (unsigned)((lane >> 4) * 8);

    for (int c = 0; c < NCHK; c++) {
        cp_wait0();
        __syncthreads();
        if (c + 1 < NCHK) {
            unsigned int dst = smb + SM_B0 + ((c + 1) & 1) * SM_BBYTES;
            const uint4* sb = (const uint4*)(g_B + (c + 1) * 4096);
#pragma unroll
            for (int u = 0; u < 4; u++)
                cp_async16(dst + (tid + u * THREADS) * 16, sb + tid + u * THREADS);
            cp_commit();
        }

        unsigned int bbase = smb + SM_B0 + (c & 1) * SM_BBYTES;
#pragma unroll
        for (int s = 0; s < CHUNK_S; s++) {
            int k0 = (c * CHUNK_S + s) * 16;
            unsigned int bw[4][2];
#pragma unroll
            for (int t = 0; t < 4; t++) {
                int T = warp * 4 + t;
                unsigned int boff = bbase + (((unsigned)(s * 32 + T) * 32 + lane) * 8);
                asm volatile("ld.shared.v2.u32 {%0,%1}, [%2];"
                             : "=r"(bw[t][0]), "=r"(bw[t][1]) : "r"(boff));
            }
#pragma unroll
            for (int i = 0; i < 4; i++) {
                unsigned int ah[4];
                unsigned int off = ((i * 16 + a_row) * ASTRIDE + k0 + a_col) * 2;
                ldmatrix4(ah, smb + off);
#pragma unroll
                for (int t = 0; t < 4; t++)
                    mma_f16(acc[i][t], ah, bw[t][0], bw[t][1]);
            }
        }
        __syncthreads();
    }

    // ---- epilogue: h = relu(acc + b1) as fp16 into smem (overlay A region)
    __syncthreads();
    unsigned short* hh = (unsigned short*)dsm;   // 64 x ASTRIDE fp16
    int g   = lane >> 2;
    int tig = lane & 3;
#pragma unroll
    for (int i = 0; i < 4; i++) {
#pragma unroll
        for (int t = 0; t < 4; t++) {
            int n = warp * 32 + t * 8 + 2 * tig;
            int m0 = i * 16 + g;
            float bb0 = b1s[n], bb1 = b1s[n + 1];
            __half v00 = __float2half_rn(fmaxf(acc[i][t][0] + bb0, 0.f));
            __half v01 = __float2half_rn(fmaxf(acc[i][t][1] + bb1, 0.f));
            __half v10 = __float2half_rn(fmaxf(acc[i][t][2] + bb0, 0.f));
            __half v11 = __float2half_rn(fmaxf(acc[i][t][3] + bb1, 0.f));
            *(unsigned int*)(hh + m0 * ASTRIDE + n)        = pack_h2(v00, v01);
            *(unsigned int*)(hh + (m0 + 8) * ASTRIDE + n)  = pack_h2(v10, v11);
        }
    }
    __syncthreads();

    // ---- GEMM2: h[64x256] (fp16) @ W2[256x8] + b2
    int e0 = tid >> 3, o = tid & 7;
    float bo = b2s[o];
#pragma unroll
    for (int pass = 0; pass < 2; pass++) {
        int e = e0 + pass * 32;
        const unsigned short* hr = hh + e * ASTRIDE;
        const float* wr = w2s + o * W2STRIDE;
        float a = bo;
#pragma unroll 8
        for (int k = 0; k < HIDDEN; k += 8) {
            uint4 hv = *(const uint4*)(hr + k);      // 8 fp16
            float4 w0 = *(const float4*)(wr + k);
            float4 w1 = *(const float4*)(wr + k + 4);
            __half2 p0 = *reinterpret_cast<__half2*>(&hv.x);
            __half2 p1 = *reinterpret_cast<__half2*>(&hv.y);
            __half2 p2 = *reinterpret_cast<__half2*>(&hv.z);
            __half2 p3 = *reinterpret_cast<__half2*>(&hv.w);
            a = fmaf(__low2float(p0),  w0.x, a);
            a = fmaf(__high2float(p0), w0.y, a);
            a = fmaf(__low2float(p1),  w0.z, a);
            a = fmaf(__high2float(p1), w0.w, a);
            a = fmaf(__low2float(p2),  w1.x, a);
            a = fmaf(__high2float(p2), w1.y, a);
            a = fmaf(__low2float(p3),  w1.z, a);
            a = fmaf(__high2float(p3), w1.w, a);
        }
        long long ge = eBase + e;
        if (ge < n_edges) out[ge * ETYPES + o] = a;
    }
}

// ---------------- launch ----------------
extern "C" void kernel_launch(void* const* d_in, const int* in_sizes, int n_in,
                              void* d_out, int out_size) {
    const float* z  = (const float*)d_in[0];
    const int*   ei = (const int*)d_in[1];
    const float* Wn = (const float*)d_in[2];
    const float* bn = (const float*)d_in[3];
    const float* W1 = (const float*)d_in[4];
    const float* b1 = (const float*)d_in[5];
    const float* W2 = (const float*)d_in[6];
    const float* b2 = (const float*)d_in[7];

    int n_nodes = in_sizes[0] / LATENT;
    int n_edges = in_sizes[1] / 2;
    float* out = (float*)d_out;

    prep_w1<<<64, 256>>>(W1);
    node_kernel<<<(n_nodes + 31) / 32, THREADS>>>(z, Wn, bn, out, n_nodes);

    cudaFuncSetAttribute(edge_kernel, cudaFuncAttributeMaxDynamicSharedMemorySize, DSMEM_BYTES);
    int grid = (n_edges + E_TILE - 1) / E_TILE;
    edge_kernel<<<grid, THREADS, DSMEM_BYTES>>>(
        z, ei, b1, W2, b2, out + (size_t)n_nodes * NTYPES, n_edges, n_nodes);
}

// round 11
// speedup vs baseline: 6.3083x; 1.4597x over previous
#include <cuda_runtime.h>
#include <cuda_fp16.h>
#include <cstdint>

#define LATENT   128
#define HIDDEN   256
#define NTYPES   32
#define ETYPES   8
#define E_TILE   64
#define THREADS  256
#define ASTRIDE  264          // fp16 elems per A row (pad: conflict-free ldmatrix)
#define CHUNK_S  2            // k16-steps per B chunk
#define NCHK     8

// dynamic smem layout (bytes):
//  A: 64*264*2 = 33792      @0   (partial-sum overlay 8 x 64 x 8 f32 = 16384 after mainloop)
//  Bbuf0: 16384             @33792
//  Bbuf1: 16384             @50176
#define SM_B0     33792
#define SM_BBYTES 16384
#define DSMEM_BYTES (33792 + 2 * 16384)

// fragment-ready packed W1 fp16 (GEMM1 B operand)
__device__ unsigned int g_B[32768];
// fragment-ready W2 fp16 hi/lo (GEMM2 B operand): idx = ((kstep*32+lane)*2 + q)
__device__ unsigned int g_B2h[1024];
__device__ unsigned int g_B2l[1024];

__device__ __forceinline__ unsigned int smem_u32(const void* p) {
    unsigned int a;
    asm("{ .reg .u64 t; cvta.to.shared.u64 t, %1; cvt.u32.u64 %0, t; }" : "=r"(a) : "l"(p));
    return a;
}
__device__ __forceinline__ unsigned int pack_h2(__half a, __half b) {
    __half2 h = __halves2half2(a, b);
    return *reinterpret_cast<unsigned int*>(&h);
}
__device__ __forceinline__ void mma_f16(float* c, const unsigned int* a,
                                        unsigned int b0, unsigned int b1) {
    asm volatile(
        "mma.sync.aligned.m16n8k16.row.col.f32.f16.f16.f32 "
        "{%0,%1,%2,%3}, {%4,%5,%6,%7}, {%8,%9}, {%0,%1,%2,%3};"
        : "+f"(c[0]), "+f"(c[1]), "+f"(c[2]), "+f"(c[3])
        : "r"(a[0]), "r"(a[1]), "r"(a[2]), "r"(a[3]), "r"(b0), "r"(b1));
}
__device__ __forceinline__ void ldmatrix4(unsigned int* r, unsigned int addr) {
    asm volatile("ldmatrix.sync.aligned.m8n8.x4.shared.b16 {%0,%1,%2,%3}, [%4];"
                 : "=r"(r[0]), "=r"(r[1]), "=r"(r[2]), "=r"(r[3]) : "r"(addr));
}
__device__ __forceinline__ void cp_async16(unsigned int dst, const void* src) {
    asm volatile("cp.async.cg.shared.global [%0], [%1], 16;" :: "r"(dst), "l"(src));
}
__device__ __forceinline__ void cp_commit() {
    asm volatile("cp.async.commit_group;" ::: "memory");
}
__device__ __forceinline__ void cp_wait0() {
    asm volatile("cp.async.wait_group 0;" ::: "memory");
}

// ---------------- prep: pack W1 into fragment-ready fp16 ----------------
__global__ void prep_w1(const float* __restrict__ W1) {
    int p = blockIdx.x * 256 + threadIdx.x;
    int l = p & 31;
    int T = (p >> 5) & 31;
    int s = p >> 10;
    int n  = T * 8 + (l >> 2);
    int kb = s * 16 + 2 * (l & 3);
#pragma unroll
    for (int q = 0; q < 2; q++) {
        int k = kb + q * 8;
        __half h0 = __float2half_rn(W1[k * HIDDEN + n]);
        __half h1 = __float2half_rn(W1[(k + 1) * HIDDEN + n]);
        g_B[p * 2 + q] = pack_h2(h0, h1);
    }
}

// ---------------- prep: pack W2 into fragment-ready fp16 hi/lo ----------------
// B fragment (col-major k16 x n8): b0=(2tig,g) b1=(2tig+1,g) b2=(2tig+8,g) b3=(2tig+9,g)
__global__ void prep_w2(const float* __restrict__ W2) {
    int p = blockIdx.x * 256 + threadIdx.x;   // 0..511
    if (p >= 512) return;
    int lane = p & 31;
    int kstep = p >> 5;                       // 0..15
    int g   = lane >> 2;
    int tig = lane & 3;
    int k0  = kstep * 16 + 2 * tig;
#pragma unroll
    for (int q = 0; q < 2; q++) {
        int k = k0 + q * 8;
        float v0 = W2[k * ETYPES + g];
        float v1 = W2[(k + 1) * ETYPES + g];
        __half h0 = __float2half_rn(v0);
        __half h1 = __float2half_rn(v1);
        g_B2h[p * 2 + q] = pack_h2(h0, h1);
        g_B2l[p * 2 + q] = pack_h2(__float2half_rn(v0 - __half2float(h0)),
                                   __float2half_rn(v1 - __half2float(h1)));
    }
}

// ---------------- node logits ----------------
__global__ void node_kernel(const float* __restrict__ z,
                            const float* __restrict__ Wn,
                            const float* __restrict__ bn,
                            float* __restrict__ out, int n_nodes) {
    __shared__ float ws[LATENT * NTYPES];
    __shared__ float zs[32 * 132];
    __shared__ float bs[NTYPES];
    int tid = threadIdx.x;
    for (int idx = tid; idx < LATENT * NTYPES / 4; idx += THREADS)
        ((float4*)ws)[idx] = ((const float4*)Wn)[idx];
    if (tid < NTYPES) bs[tid] = bn[tid];
    long long nBase = (long long)blockIdx.x * 32;
    for (int idx = tid; idx < 32 * LATENT / 4; idx += THREADS) {
        int n = idx / (LATENT / 4), kk = idx % (LATENT / 4);
        long long gn = nBase + n;
        float4 v = make_float4(0.f, 0.f, 0.f, 0.f);
        if (gn < n_nodes) v = *(const float4*)(z + gn * LATENT + kk * 4);
        *(float4*)(zs + n * 132 + kk * 4) = v;
    }
    __syncthreads();
    int n = tid >> 3, tg = tid & 7;
    float a0 = bs[tg*4+0], a1 = bs[tg*4+1], a2 = bs[tg*4+2], a3 = bs[tg*4+3];
    const float* zr = zs + n * 132;
#pragma unroll 8
    for (int k = 0; k < LATENT; k++) {
        float zv = zr[k];
        float4 w = *(const float4*)(ws + k * NTYPES + tg * 4);
        a0 = fmaf(zv, w.x, a0); a1 = fmaf(zv, w.y, a1);
        a2 = fmaf(zv, w.z, a2); a3 = fmaf(zv, w.w, a3);
    }
    long long gn = nBase + n;
    if (gn < n_nodes)
        *(float4*)(out + gn * NTYPES + tg * 4) = make_float4(a0, a1, a2, a3);
}

// ---------------- edge kernel: fp16 mma.sync GEMM1 + fragment-fused GEMM2 ----
__global__ void __launch_bounds__(THREADS, 2)
edge_kernel(const float* __restrict__ z,
            const int* __restrict__ ei,
            const float* __restrict__ b1,
            const float* __restrict__ b2,
            float* __restrict__ out,
            int n_edges, int n_nodes) {
    extern __shared__ char dsm[];
    __shared__ int   idx_r[E_TILE];
    __shared__ int   idx_c[E_TILE];
    __shared__ float b1s[HIDDEN];
    __shared__ float b2s[ETYPES];

    int tid  = threadIdx.x;
    int lane = tid & 31;
    int warp = tid >> 5;
    long long eBase = (long long)blockIdx.x * E_TILE;

    unsigned int smb = smem_u32(dsm);

    // ---- prefetch B chunk 0
    {
        unsigned int dst = smb + SM_B0;
        const uint4* sb = (const uint4*)g_B;
#pragma unroll
        for (int u = 0; u < 4; u++)
            cp_async16(dst + (tid + u * THREADS) * 16, sb + tid + u * THREADS);
        cp_commit();
    }

    // ---- stage b1 / b2 / edge indices
    if (tid < HIDDEN) b1s[tid] = b1[tid];
    if (tid < ETYPES) b2s[tid] = b2[tid];
    if (tid < E_TILE) {
        long long e = eBase + tid;
        if (e >= n_edges) e = n_edges - 1;
        int r = ei[e];
        int c = ei[(long long)n_edges + e];
        idx_r[tid] = min(max(r, 0), n_nodes - 1);
        idx_c[tid] = min(max(c, 0), n_nodes - 1);
    }
    __syncthreads();

    // ---- gather A: 64 edges x 256 k, fp16
    {
        int e_loc = tid >> 2;
        int quarter = tid & 3;
        int node = (quarter < 2) ? idx_r[e_loc] : idx_c[e_loc];
        const float* src = z + (long long)node * LATENT + (quarter & 1) * 64;
        unsigned short* Ah = (unsigned short*)dsm;
        int base = e_loc * ASTRIDE + quarter * 64;
#pragma unroll
        for (int g = 0; g < 16; g++) {
            float4 v = *(const float4*)(src + g * 4);
            unsigned int* ph = (unsigned int*)(Ah + base + g * 4);
            ph[0] = pack_h2(__float2half_rn(v.x), __float2half_rn(v.y));
            ph[1] = pack_h2(__float2half_rn(v.z), __float2half_rn(v.w));
        }
    }

    // ---- mainloop (GEMM1)
    float acc[4][4][4];
#pragma unroll
    for (int i = 0; i < 4; i++)
#pragma unroll
        for (int t = 0; t < 4; t++)
#pragma unroll
            for (int r = 0; r < 4; r++) acc[i][t][r] = 0.f;

    unsigned int a_row = (unsigned)(lane & 15);
    unsigned int a_col = (unsigned)((lane >> 4) * 8);

    for (int c = 0; c < NCHK; c++) {
        cp_wait0();
        __syncthreads();
        if (c + 1 < NCHK) {
            unsigned int dst = smb + SM_B0 + ((c + 1) & 1) * SM_BBYTES;
            const uint4* sb = (const uint4*)(g_B + (c + 1) * 4096);
#pragma unroll
            for (int u = 0; u < 4; u++)
                cp_async16(dst + (tid + u * THREADS) * 16, sb + tid + u * THREADS);
            cp_commit();
        }

        unsigned int bbase = smb + SM_B0 + (c & 1) * SM_BBYTES;
#pragma unroll
        for (int s = 0; s < CHUNK_S; s++) {
            int k0 = (c * CHUNK_S + s) * 16;
            unsigned int bw[4][2];
#pragma unroll
            for (int t = 0; t < 4; t++) {
                int T = warp * 4 + t;
                unsigned int boff = bbase + (((unsigned)(s * 32 + T) * 32 + lane) * 8);
                asm volatile("ld.shared.v2.u32 {%0,%1}, [%2];"
                             : "=r"(bw[t][0]), "=r"(bw[t][1]) : "r"(boff));
            }
#pragma unroll
            for (int i = 0; i < 4; i++) {
                unsigned int ah[4];
                unsigned int off = ((i * 16 + a_row) * ASTRIDE + k0 + a_col) * 2;
                ldmatrix4(ah, smb + off);
#pragma unroll
                for (int t = 0; t < 4; t++)
                    mma_f16(acc[i][t], ah, bw[t][0], bw[t][1]);
            }
        }
        __syncthreads();
    }

    // ---- GEMM2 in registers: relu(acc + b1) fragments -> mma against W2 frags
    // warp owns h cols [warp*32, warp*32+32) for all 64 rows -> 2 k16-steps
    int g   = lane >> 2;
    int tig = lane & 3;
    float cacc[4][4];
#pragma unroll
    for (int i = 0; i < 4; i++)
#pragma unroll
        for (int r = 0; r < 4; r++) cacc[i][r] = 0.f;

#pragma unroll
    for (int s2 = 0; s2 < 2; s2++) {
        int kstep = warp * 2 + s2;
        // B fragments (hi/lo) from prepped global
        uint2 bh = *(const uint2*)(g_B2h + (kstep * 32 + lane) * 2);
        uint2 bl = *(const uint2*)(g_B2l + (kstep * 32 + lane) * 2);
        // bias at this thread's h columns
        int cb = warp * 32 + s2 * 16 + 2 * tig;
        float f0 = b1s[cb],     f1 = b1s[cb + 1];
        float f8 = b1s[cb + 8], f9 = b1s[cb + 9];
#pragma unroll
        for (int i = 0; i < 4; i++) {
            float* cA = acc[i][2 * s2];       // n8 tile covering k-cols [0,8) of k16
            float* cB = acc[i][2 * s2 + 1];   // k-cols [8,16)
            unsigned int afr[4];
            afr[0] = pack_h2(__float2half_rn(fmaxf(cA[0] + f0, 0.f)),
                             __float2half_rn(fmaxf(cA[1] + f1, 0.f)));
            afr[1] = pack_h2(__float2half_rn(fmaxf(cA[2] + f0, 0.f)),
                             __float2half_rn(fmaxf(cA[3] + f1, 0.f)));
            afr[2] = pack_h2(__float2half_rn(fmaxf(cB[0] + f8, 0.f)),
                             __float2half_rn(fmaxf(cB[1] + f9, 0.f)));
            afr[3] = pack_h2(__float2half_rn(fmaxf(cB[2] + f8, 0.f)),
                             __float2half_rn(fmaxf(cB[3] + f9, 0.f)));
            mma_f16(cacc[i], afr, bh.x, bh.y);
            mma_f16(cacc[i], afr, bl.x, bl.y);
        }
    }

    // ---- cross-warp reduction of partial m64 x 8 results
    __syncthreads();                       // A smem dead; reuse as partial buffers
    float* part = (float*)dsm;             // 8 warps x 512 floats
    float* pw = part + warp * 512;
#pragma unroll
    for (int i = 0; i < 4; i++) {
        int m0 = i * 16 + g;
        *(float2*)(pw + m0 * 8 + 2 * tig)       = make_float2(cacc[i][0], cacc[i][1]);
        *(float2*)(pw + (m0 + 8) * 8 + 2 * tig) = make_float2(cacc[i][2], cacc[i][3]);
    }
    __syncthreads();

#pragma unroll
    for (int rep = 0; rep < 2; rep++) {
        int idx = tid + rep * THREADS;     // 0..511 -> (m, o)
        float s = b2s[idx & 7];
#pragma unroll
        for (int w = 0; w < 8; w++) s += part[w * 512 + idx];
        long long ge = eBase + (idx >> 3);
        if (ge < n_edges) out[ge * ETYPES + (idx & 7)] = s;
    }
}

// ---------------- launch ----------------
extern "C" void kernel_launch(void* const* d_in, const int* in_sizes, int n_in,
                              void* d_out, int out_size) {
    const float* z  = (const float*)d_in[0];
    const int*   ei = (const int*)d_in[1];
    const float* Wn = (const float*)d_in[2];
    const float* bn = (const float*)d_in[3];
    const float* W1 = (const float*)d_in[4];
    const float* b1 = (const float*)d_in[5];
    const float* W2 = (const float*)d_in[6];
    const float* b2 = (const float*)d_in[7];

    int n_nodes = in_sizes[0] / LATENT;
    int n_edges = in_sizes[1] / 2;
    float* out = (float*)d_out;

    prep_w1<<<64, 256>>>(W1);
    prep_w2<<<2, 256>>>(W2);
    node_kernel<<<(n_nodes + 31) / 32, THREADS>>>(z, Wn, bn, out, n_nodes);

    cudaFuncSetAttribute(edge_kernel, cudaFuncAttributeMaxDynamicSharedMemorySize, DSMEM_BYTES);
    int grid = (n_edges + E_TILE - 1) / E_TILE;
    edge_kernel<<<grid, THREADS, DSMEM_BYTES>>>(
        z, ei, b1, b2, out + (size_t)n_nodes * NTYPES, n_edges, n_nodes);
}